// round 1
// baseline (speedup 1.0000x reference)
#include <cuda_runtime.h>
#include <cuda_bf16.h>
#include <math.h>
#include <stdint.h>

// ---------------------------------------------------------------------------
// PointNet++ encoder: 3 SA layers.
//   B=8, N=4096. L1: m=2048 r=0.2 (3->32->32). L2: m=512 r=0.4 (32->64->64).
//   L3: m=512 r=1.0 (64->128->128). k=64 neighbors.
// Output = concat(x3 [8,512,128], p3 [8,512,3], batch [8,512]) as float32.
// ---------------------------------------------------------------------------

#define BB   8
#define N1   4096
#define M1   2048
#define M2   512
#define M3   512
#define KNBR 64

// ------------------------------ scratch ------------------------------------
__device__ float g_p1[BB * M1 * 3];
__device__ float g_x1[BB * M1 * 32];
__device__ int   g_idx1[BB * M1];
__device__ float g_p2[BB * M2 * 3];
__device__ float g_x2[BB * M2 * 64];
__device__ int   g_idx2[BB * M2];
__device__ float g_p3[BB * M3 * 3];
__device__ int   g_idx3[BB * M3];
__device__ int   g_nbr1[BB * M1 * KNBR];
__device__ int   g_cnt1[BB * M1];
__device__ int   g_nbr2[BB * M2 * KNBR];
__device__ int   g_cnt2[BB * M2];
__device__ int   g_nbr3[BB * M3 * KNBR];
__device__ int   g_cnt3[BB * M3];

// ------------------------------ FPS ----------------------------------------
// One block per batch. Points cached in smem (for winner coords) + registers.
// Matches reference arithmetic: d2 = fma(dz,dz, fma(dy,dy, dx*dx)); running
// fminf; argmax with first-index tie-break.
template <int N, int M, int TPB>
__global__ void __launch_bounds__(TPB)
fps_kernel(const float* __restrict__ pos, float* __restrict__ pos_out,
           int* __restrict__ idx_out) {
    constexpr int P  = N / TPB;
    constexpr int NW = TPB / 32;
    extern __shared__ float sm[];
    float* sx   = sm;
    float* sy   = sm + N;
    float* sz   = sm + 2 * N;
    float* bc   = sm + 3 * N;         // 3 floats: selected coords
    float* redv = bc + 3;             // NW floats
    int*   redi = (int*)(redv + NW);  // NW ints

    const int b = blockIdx.x;
    const int t = threadIdx.x;
    const int lane = t & 31, wid = t >> 5;
    const float* pb = pos + (size_t)b * N * 3;

    for (int i = t; i < N; i += TPB) {
        sx[i] = pb[i * 3 + 0];
        sy[i] = pb[i * 3 + 1];
        sz[i] = pb[i * 3 + 2];
    }
    __syncthreads();

    float rx[P], ry[P], rz[P], md[P];
    const float x0 = sx[0], y0 = sy[0], z0 = sz[0];
#pragma unroll
    for (int j = 0; j < P; j++) {
        int id = t + j * TPB;
        rx[j] = sx[id]; ry[j] = sy[id]; rz[j] = sz[id];
        float dx = rx[j] - x0, dy = ry[j] - y0, dz = rz[j] - z0;
        md[j] = fmaf(dz, dz, fmaf(dy, dy, dx * dx));
    }
    if (t == 0) {
        idx_out[(size_t)b * M] = 0;
        pos_out[(size_t)b * M * 3 + 0] = x0;
        pos_out[(size_t)b * M * 3 + 1] = y0;
        pos_out[(size_t)b * M * 3 + 2] = z0;
    }

    for (int s = 1; s < M; s++) {
        // local argmax (ids ascend with j -> strict > keeps first index)
        float bv = md[0];
        int   bi = t;
#pragma unroll
        for (int j = 1; j < P; j++) {
            if (md[j] > bv) { bv = md[j]; bi = t + j * TPB; }
        }
        // warp reduce (prefer larger value; ties -> smaller index)
#pragma unroll
        for (int off = 16; off > 0; off >>= 1) {
            float ov = __shfl_down_sync(0xffffffffu, bv, off);
            int   oi = __shfl_down_sync(0xffffffffu, bi, off);
            if (ov > bv || (ov == bv && oi < bi)) { bv = ov; bi = oi; }
        }
        if (lane == 0) { redv[wid] = bv; redi[wid] = bi; }
        __syncthreads();
        if (wid == 0) {
            float v  = (lane < NW) ? redv[lane] : -INFINITY;
            int   i2 = (lane < NW) ? redi[lane] : 0x7fffffff;
#pragma unroll
            for (int off = 16; off > 0; off >>= 1) {
                float ov = __shfl_down_sync(0xffffffffu, v, off);
                int   oi = __shfl_down_sync(0xffffffffu, i2, off);
                if (ov > v || (ov == v && oi < i2)) { v = ov; i2 = oi; }
            }
            if (lane == 0) {
                float cx = sx[i2], cy = sy[i2], cz = sz[i2];
                bc[0] = cx; bc[1] = cy; bc[2] = cz;
                idx_out[(size_t)b * M + s] = i2;
                pos_out[((size_t)b * M + s) * 3 + 0] = cx;
                pos_out[((size_t)b * M + s) * 3 + 1] = cy;
                pos_out[((size_t)b * M + s) * 3 + 2] = cz;
            }
        }
        __syncthreads();
        const float cx = bc[0], cy = bc[1], cz = bc[2];
#pragma unroll
        for (int j = 0; j < P; j++) {
            float dx = rx[j] - cx, dy = ry[j] - cy, dz = rz[j] - cz;
            float d  = fmaf(dz, dz, fmaf(dy, dy, dx * dx));
            md[j] = fminf(md[j], d);
        }
    }
}

// ------------------------------ ball query ---------------------------------
// One 128-thread block per query. Compact in-radius candidates to smem, then
// rank-select the 64 nearest (rank r entry written to slot r -> exactly the
// k-nearest set, sorted, like lax.top_k).
template <int NSRC>
__global__ void __launch_bounds__(128)
ballq_kernel(const float* __restrict__ pos_src, const float* __restrict__ pos_q,
             int* __restrict__ nbr, int* __restrict__ cnt, float rsq, int M) {
    __shared__ unsigned int s_keys[NSRC];
    __shared__ int s_idx[NSRC];
    __shared__ int s_counter;

    const int q = blockIdx.x;
    const int b = q / M;
    const int t = threadIdx.x;
    if (t == 0) s_counter = 0;
    __syncthreads();

    const float qx = pos_q[q * 3 + 0];
    const float qy = pos_q[q * 3 + 1];
    const float qz = pos_q[q * 3 + 2];
    const float qn = fmaf(qz, qz, fmaf(qy, qy, qx * qx));
    const float* ps = pos_src + (size_t)b * NSRC * 3;

    for (int i = t; i < NSRC; i += 128) {
        float sxx = ps[i * 3 + 0], syy = ps[i * 3 + 1], szz = ps[i * 3 + 2];
        float sn  = fmaf(szz, szz, fmaf(syy, syy, sxx * sxx));
        float dot = fmaf(qz, szz, fmaf(qy, syy, qx * sxx));
        float d2  = fmaf(-2.0f, dot, qn + sn);
        if (d2 <= rsq) {
            int p = atomicAdd(&s_counter, 1);
            unsigned u = __float_as_uint(d2);
            u = ((int)u >= 0) ? (u ^ 0x80000000u) : ~u;   // monotone f32->u32
            s_keys[p] = u;
            s_idx[p]  = i;
        }
    }
    __syncthreads();
    const int c = s_counter;

    int* onbr = nbr + (size_t)q * KNBR;
    for (int e = t; e < c; e += 128) {
        unsigned k = s_keys[e];
        int r = 0;
        for (int j = 0; j < c; j++) {
            unsigned kj = s_keys[j];                       // broadcast read
            r += (kj < k) || (kj == k && j < e);
        }
        if (r < KNBR) onbr[r] = s_idx[e];
    }
    if (t == 0) cnt[q] = (c < KNBR) ? c : KNBR;
}

// ------------------------------ fused MLP + max ----------------------------
// One warp per query, 8 warps/block, weights in shared, neighbors batched by 4
// to amortize weight loads. Channel c owned by lane (c = lane + 32*r).
template <int CIN, int CMID, int COUT>
__global__ void __launch_bounds__(256)
mlp_kernel(const float* __restrict__ x_src, const float* __restrict__ pos_src,
           const float* __restrict__ pos_q, const int* __restrict__ nbr,
           const int* __restrict__ cnt, float* __restrict__ out,
           const float* __restrict__ w1, const float* __restrict__ b1,
           const float* __restrict__ w2, const float* __restrict__ b2,
           int NSRC, int M) {
    constexpr int MSG = CIN + 3;
    constexpr int NB  = 4;
    constexpr int R1  = CMID / 32;
    constexpr int R2  = COUT / 32;
    constexpr int WPB = 8;

    extern __shared__ float sm[];
    float* sw1  = sm;                        // MSG*CMID
    float* sb1  = sw1 + MSG * CMID;          // CMID
    float* sw2  = sb1 + CMID;                // CMID*COUT
    float* sb2  = sw2 + CMID * COUT;         // COUT
    float* smsg = sb2 + COUT;                // WPB*NB*MSG
    float* sh1  = smsg + WPB * NB * MSG;     // WPB*NB*CMID

    const int t = threadIdx.x;
    for (int i = t; i < MSG * CMID; i += 256) sw1[i] = w1[i];
    for (int i = t; i < CMID; i += 256) sb1[i] = b1[i];
    for (int i = t; i < CMID * COUT; i += 256) sw2[i] = w2[i];
    for (int i = t; i < COUT; i += 256) sb2[i] = b2[i];
    __syncthreads();

    const int w = t >> 5, lane = t & 31;
    const int q = blockIdx.x * WPB + w;
    const int b = q / M;
    const int kcnt = cnt[q];
    const float qx = pos_q[q * 3 + 0];
    const float qy = pos_q[q * 3 + 1];
    const float qz = pos_q[q * 3 + 2];
    float* msg = smsg + w * NB * MSG;
    float* h1  = sh1 + w * NB * CMID;
    const int* nb_ptr = nbr + (size_t)q * KNBR;
    const float* xs = x_src + (size_t)b * NSRC * CIN;
    const float* ps = pos_src + (size_t)b * NSRC * 3;

    float bias1[R1], bias2[R2];
#pragma unroll
    for (int r = 0; r < R1; r++) bias1[r] = sb1[lane + 32 * r];
#pragma unroll
    for (int r = 0; r < R2; r++) bias2[r] = sb2[lane + 32 * r];

    float vmax[R2];
#pragma unroll
    for (int r = 0; r < R2; r++) vmax[r] = -INFINITY;

    for (int n0 = 0; n0 < kcnt; n0 += NB) {
        const int nv = min(NB, kcnt - n0);
        // fill msg buffers for this neighbor batch
        for (int e = lane; e < NB * MSG; e += 32) {
            int nbn = e / MSG, i = e - nbn * MSG;
            float v = 0.0f;
            if (nbn < nv) {
                int nid = nb_ptr[n0 + nbn];
                if (i < CIN) {
                    v = xs[(size_t)nid * CIN + i];
                } else {
                    float qc = (i == CIN) ? qx : ((i == CIN + 1) ? qy : qz);
                    v = ps[nid * 3 + (i - CIN)] - qc;
                }
            }
            msg[e] = v;
        }
        __syncwarp();
        // layer 1: h1 = relu(msg @ w1 + b1)
        float acc[NB][R1];
#pragma unroll
        for (int nbn = 0; nbn < NB; nbn++)
#pragma unroll
            for (int r = 0; r < R1; r++) acc[nbn][r] = bias1[r];
        for (int i = 0; i < MSG; i++) {
            float wv[R1];
#pragma unroll
            for (int r = 0; r < R1; r++) wv[r] = sw1[i * CMID + lane + 32 * r];
#pragma unroll
            for (int nbn = 0; nbn < NB; nbn++) {
                float mv = msg[nbn * MSG + i];
#pragma unroll
                for (int r = 0; r < R1; r++)
                    acc[nbn][r] = fmaf(mv, wv[r], acc[nbn][r]);
            }
        }
#pragma unroll
        for (int nbn = 0; nbn < NB; nbn++)
#pragma unroll
            for (int r = 0; r < R1; r++)
                h1[nbn * CMID + lane + 32 * r] = fmaxf(acc[nbn][r], 0.0f);
        __syncwarp();
        // layer 2: out = h1 @ w2 + b2, max-aggregate over valid neighbors
        float acc2[NB][R2];
#pragma unroll
        for (int nbn = 0; nbn < NB; nbn++)
#pragma unroll
            for (int r = 0; r < R2; r++) acc2[nbn][r] = bias2[r];
        for (int j = 0; j < CMID; j++) {
            float wv[R2];
#pragma unroll
            for (int r = 0; r < R2; r++) wv[r] = sw2[j * COUT + lane + 32 * r];
#pragma unroll
            for (int nbn = 0; nbn < NB; nbn++) {
                float hv = h1[nbn * CMID + j];
#pragma unroll
                for (int r = 0; r < R2; r++)
                    acc2[nbn][r] = fmaf(hv, wv[r], acc2[nbn][r]);
            }
        }
#pragma unroll
        for (int nbn = 0; nbn < NB; nbn++) {
            if (nbn < nv) {
#pragma unroll
                for (int r = 0; r < R2; r++)
                    vmax[r] = fmaxf(vmax[r], acc2[nbn][r]);
            }
        }
        __syncwarp();
    }
#pragma unroll
    for (int r = 0; r < R2; r++)
        out[(size_t)q * COUT + lane + 32 * r] = (kcnt > 0) ? vmax[r] : 0.0f;
}

// ------------------------------ output pack --------------------------------
__global__ void pack_kernel(const float* __restrict__ p3, float* __restrict__ out) {
    const int X3  = BB * M3 * 128;        // 524288
    const int P3S = BB * M3 * 3;          // 12288
    int i = blockIdx.x * 256 + threadIdx.x;
    if (i < P3S) out[X3 + i] = p3[i];
    if (i < BB * M3) out[X3 + P3S + i] = (float)(i >> 9);  // batch id b = i/512
}

// ------------------------------ host launch --------------------------------
static inline size_t fps_smem(int N, int TPB) {
    return (size_t)(3 * N + 3 + 2 * (TPB / 32)) * 4;
}
static inline size_t mlp_smem(int CIN, int CMID, int COUT) {
    int MSG = CIN + 3;
    return (size_t)(MSG * CMID + CMID + CMID * COUT + COUT +
                    8 * 4 * MSG + 8 * 4 * CMID) * 4;
}

extern "C" void kernel_launch(void* const* d_in, const int* in_sizes, int n_in,
                              void* d_out, int out_size) {
    const float* pos = (const float*)d_in[0];
    // d_in[1] = batch (unused; values reconstructed in pack_kernel)
    const float* w11 = (const float*)d_in[2];
    const float* b11 = (const float*)d_in[3];
    const float* w12 = (const float*)d_in[4];
    const float* b12 = (const float*)d_in[5];
    const float* w21 = (const float*)d_in[6];
    const float* b21 = (const float*)d_in[7];
    const float* w22 = (const float*)d_in[8];
    const float* b22 = (const float*)d_in[9];
    const float* w31 = (const float*)d_in[10];
    const float* b31 = (const float*)d_in[11];
    const float* w32 = (const float*)d_in[12];
    const float* b32 = (const float*)d_in[13];
    float* out = (float*)d_out;

    float *p1, *x1, *p2, *x2, *p3;
    int *idx1, *idx2, *idx3, *nbr1, *cnt1, *nbr2, *cnt2, *nbr3, *cnt3;
    cudaGetSymbolAddress((void**)&p1, g_p1);
    cudaGetSymbolAddress((void**)&x1, g_x1);
    cudaGetSymbolAddress((void**)&idx1, g_idx1);
    cudaGetSymbolAddress((void**)&p2, g_p2);
    cudaGetSymbolAddress((void**)&x2, g_x2);
    cudaGetSymbolAddress((void**)&idx2, g_idx2);
    cudaGetSymbolAddress((void**)&p3, g_p3);
    cudaGetSymbolAddress((void**)&idx3, g_idx3);
    cudaGetSymbolAddress((void**)&nbr1, g_nbr1);
    cudaGetSymbolAddress((void**)&cnt1, g_cnt1);
    cudaGetSymbolAddress((void**)&nbr2, g_nbr2);
    cudaGetSymbolAddress((void**)&cnt2, g_cnt2);
    cudaGetSymbolAddress((void**)&nbr3, g_nbr3);
    cudaGetSymbolAddress((void**)&cnt3, g_cnt3);

    // opt-in smem sizes (idempotent; capture-safe host calls)
    cudaFuncSetAttribute(fps_kernel<N1, M1, 512>,
                         cudaFuncAttributeMaxDynamicSharedMemorySize,
                         (int)fps_smem(N1, 512));
    cudaFuncSetAttribute(fps_kernel<M1, M2, 512>,
                         cudaFuncAttributeMaxDynamicSharedMemorySize,
                         (int)fps_smem(M1, 512));
    cudaFuncSetAttribute(fps_kernel<M2, M3, 512>,
                         cudaFuncAttributeMaxDynamicSharedMemorySize,
                         (int)fps_smem(M2, 512));
    cudaFuncSetAttribute(mlp_kernel<3, 32, 32>,
                         cudaFuncAttributeMaxDynamicSharedMemorySize,
                         (int)mlp_smem(3, 32, 32));
    cudaFuncSetAttribute(mlp_kernel<32, 64, 64>,
                         cudaFuncAttributeMaxDynamicSharedMemorySize,
                         (int)mlp_smem(32, 64, 64));
    cudaFuncSetAttribute(mlp_kernel<64, 128, 128>,
                         cudaFuncAttributeMaxDynamicSharedMemorySize,
                         (int)mlp_smem(64, 128, 128));

    const float RSQ1 = (float)(0.2 * 0.2);
    const float RSQ2 = (float)(0.4 * 0.4);
    const float RSQ3 = (float)(1.0 * 1.0);

    // ---- Layer 1 ----
    fps_kernel<N1, M1, 512><<<BB, 512, fps_smem(N1, 512)>>>(pos, p1, idx1);
    ballq_kernel<N1><<<BB * M1, 128>>>(pos, p1, nbr1, cnt1, RSQ1, M1);
    mlp_kernel<3, 32, 32><<<BB * M1 / 8, 256, mlp_smem(3, 32, 32)>>>(
        pos, pos, p1, nbr1, cnt1, x1, w11, b11, w12, b12, N1, M1);

    // ---- Layer 2 ----
    fps_kernel<M1, M2, 512><<<BB, 512, fps_smem(M1, 512)>>>(p1, p2, idx2);
    ballq_kernel<M1><<<BB * M2, 128>>>(p1, p2, nbr2, cnt2, RSQ2, M2);
    mlp_kernel<32, 64, 64><<<BB * M2 / 8, 256, mlp_smem(32, 64, 64)>>>(
        x1, p1, p2, nbr2, cnt2, x2, w21, b21, w22, b22, M1, M2);

    // ---- Layer 3 ----
    fps_kernel<M2, M3, 512><<<BB, 512, fps_smem(M2, 512)>>>(p2, p3, idx3);
    ballq_kernel<M2><<<BB * M3, 128>>>(p2, p3, nbr3, cnt3, RSQ3, M3);
    mlp_kernel<64, 128, 128><<<BB * M3 / 8, 256, mlp_smem(64, 128, 128)>>>(
        x2, p2, p3, nbr3, cnt3, out, w31, b31, w32, b32, M2, M3);

    // ---- Pack p3 + batch into tail of output ----
    pack_kernel<<<(BB * M3 * 3 + 255) / 256, 256>>>(p3, out);
}

// round 2
// speedup vs baseline: 1.4238x; 1.4238x over previous
#include <cuda_runtime.h>
#include <cuda_bf16.h>
#include <math.h>
#include <stdint.h>

// ---------------------------------------------------------------------------
// PointNet++ encoder: 3 SA layers. B=8, N=4096.
// L1: m=2048 r=0.2 (3->32->32). L2: m=512 r=0.4 (32->64->64).
// L3: m=512 r=1.0 (64->128->128). k=64.
// Output = concat(x3 [8,512,128], p3 [8,512,3], batch [8,512]) as f32.
//
// Launch plan (overlap via blockIdx role dispatch, no extra streams):
//   1. fps1                      (pos -> p1)
//   2. combo2: fps2 | ballq1     (p1 -> p2 ; nbr1)
//   3. combo3: fps3 | mlp1 | ballq2
//   4. combo4: mlp2 | ballq3 | pack
//   5. mlp3 -> out
// ---------------------------------------------------------------------------

#define BB   8
#define N1   4096
#define M1   2048
#define M2   512
#define M3   512
#define KNBR 64
#define TPB  256

// ------------------------------ scratch ------------------------------------
__device__ float g_p1[BB * M1 * 3];
__device__ float g_x1[BB * M1 * 32];
__device__ float g_p2[BB * M2 * 3];
__device__ float g_x2[BB * M2 * 64];
__device__ float g_p3[BB * M3 * 3];
__device__ int   g_nbr1[BB * M1 * KNBR];
__device__ int   g_cnt1[BB * M1];
__device__ int   g_nbr2[BB * M2 * KNBR];
__device__ int   g_cnt2[BB * M2];
__device__ int   g_nbr3[BB * M3 * KNBR];
__device__ int   g_cnt3[BB * M3];

// ------------------------------ FPS (device role) ---------------------------
// One block per batch. Points in smem + registers. One __syncthreads per step:
// warp-level REDUX (max key, then min index among ties), per-warp results in
// double-buffered smem slots, then every thread scans the NW entries.
// Exact reference arithmetic: d2 = fma(dz,dz, fma(dy,dy, dx*dx)); fminf;
// argmax tie-break = first (smallest) index at every stage.
template <int N, int M>
__device__ __forceinline__ void fps_impl(const float* __restrict__ pb,
                                         float* __restrict__ po) {
    constexpr int P  = N / TPB;
    constexpr int NW = TPB / 32;
    extern __shared__ char smraw[];
    float*    sx = (float*)smraw;
    float*    sy = sx + N;
    float*    sz = sy + N;
    unsigned* kb = (unsigned*)(sz + N);   // [2][NW]
    int*      ib = (int*)(kb + 2 * NW);   // [2][NW]

    const int t = threadIdx.x;
    const int lane = t & 31, wid = t >> 5;

    for (int i = t; i < N; i += TPB) {
        sx[i] = pb[3 * i + 0];
        sy[i] = pb[3 * i + 1];
        sz[i] = pb[3 * i + 2];
    }
    __syncthreads();

    float rx[P], ry[P], rz[P], md[P];
    const float x0 = sx[0], y0 = sy[0], z0 = sz[0];
#pragma unroll
    for (int j = 0; j < P; j++) {
        int id = t + j * TPB;
        rx[j] = sx[id]; ry[j] = sy[id]; rz[j] = sz[id];
        float dx = rx[j] - x0, dy = ry[j] - y0, dz = rz[j] - z0;
        md[j] = fmaf(dz, dz, fmaf(dy, dy, dx * dx));
    }
    if (t == 0) { po[0] = x0; po[1] = y0; po[2] = z0; }

    for (int s = 1; s < M; s++) {
        // local argmax (ascending j = ascending index -> strict > keeps first)
        float bv = md[0];
        int   bi = t;
#pragma unroll
        for (int j = 1; j < P; j++) {
            if (md[j] > bv) { bv = md[j]; bi = t + j * TPB; }
        }
        // md >= 0 -> float bits are order-preserving as unsigned
        unsigned key  = __float_as_uint(bv);
        unsigned wmax = __reduce_max_sync(0xffffffffu, key);
        int cand = (key == wmax) ? bi : 0x7fffffff;
        int wbi  = __reduce_min_sync(0xffffffffu, cand);
        const int par = (s & 1) * NW;
        if (lane == 0) { kb[par + wid] = wmax; ib[par + wid] = wbi; }
        __syncthreads();
        unsigned bk = kb[par];
        int      bx = ib[par];
#pragma unroll
        for (int w2 = 1; w2 < NW; w2++) {
            unsigned k2 = kb[par + w2];
            int      i2 = ib[par + w2];
            if (k2 > bk || (k2 == bk && i2 < bx)) { bk = k2; bx = i2; }
        }
        const float cx = sx[bx], cy = sy[bx], cz = sz[bx];
        if (t == 0) { po[3 * s] = cx; po[3 * s + 1] = cy; po[3 * s + 2] = cz; }
#pragma unroll
        for (int j = 0; j < P; j++) {
            float dx = rx[j] - cx, dy = ry[j] - cy, dz = rz[j] - cz;
            md[j] = fminf(md[j], fmaf(dz, dz, fmaf(dy, dy, dx * dx)));
        }
    }
}

static __host__ __device__ constexpr size_t fps_bytes(int N) {
    return (size_t)(3 * N) * 4 + 2 * (TPB / 32) * 8;
}

// ------------------------------ ball query (device role) --------------------
template <int NSRC>
__device__ __forceinline__ void ballq_impl(int q, const float* __restrict__ pos_src,
                                           const float* __restrict__ pos_q,
                                           int* __restrict__ nbr, int* __restrict__ cnt,
                                           float rsq, int Mq) {
    extern __shared__ char smraw[];
    unsigned* s_keys = (unsigned*)smraw;
    int* s_idx = (int*)(s_keys + NSRC);
    int* s_counter = s_idx + NSRC;

    const int b = q / Mq;
    const int t = threadIdx.x;
    if (t == 0) *s_counter = 0;
    __syncthreads();

    const float qx = pos_q[q * 3 + 0];
    const float qy = pos_q[q * 3 + 1];
    const float qz = pos_q[q * 3 + 2];
    const float qn = fmaf(qz, qz, fmaf(qy, qy, qx * qx));
    const float* ps = pos_src + (size_t)b * NSRC * 3;

    for (int i = t; i < NSRC; i += TPB) {
        float sxx = ps[i * 3 + 0], syy = ps[i * 3 + 1], szz = ps[i * 3 + 2];
        float sn  = fmaf(szz, szz, fmaf(syy, syy, sxx * sxx));
        float dot = fmaf(qz, szz, fmaf(qy, syy, qx * sxx));
        float d2  = fmaf(-2.0f, dot, qn + sn);
        if (d2 <= rsq) {
            int p = atomicAdd(s_counter, 1);
            unsigned u = __float_as_uint(d2);
            u = ((int)u >= 0) ? (u ^ 0x80000000u) : ~u;   // monotone f32->u32
            s_keys[p] = u;
            s_idx[p]  = i;
        }
    }
    __syncthreads();
    const int c = *s_counter;

    int* onbr = nbr + (size_t)q * KNBR;
    for (int e = t; e < c; e += TPB) {
        unsigned k = s_keys[e];
        int r = 0;
        for (int j = 0; j < c; j++) {
            unsigned kj = s_keys[j];
            r += (kj < k) || (kj == k && j < e);
        }
        if (r < KNBR) onbr[r] = s_idx[e];
    }
    if (t == 0) cnt[q] = (c < KNBR) ? c : KNBR;
}

static __host__ __device__ constexpr size_t ballq_bytes(int NSRC) {
    return (size_t)NSRC * 8 + 16;
}

// ------------------------------ MLP (device role) ---------------------------
template <int V>
__device__ __forceinline__ void vldf(float* d, const float* s) {
    if constexpr (V == 4) { float4 v = *(const float4*)s; d[0]=v.x; d[1]=v.y; d[2]=v.z; d[3]=v.w; }
    else if constexpr (V == 2) { float2 v = *(const float2*)s; d[0]=v.x; d[1]=v.y; }
    else { d[0] = s[0]; }
}
template <int V>
__device__ __forceinline__ void vstf(float* d, const float* s) {
    if constexpr (V == 4) { *(float4*)d = make_float4(s[0], s[1], s[2], s[3]); }
    else if constexpr (V == 2) { *(float2*)d = make_float2(s[0], s[1]); }
    else { d[0] = s[0]; }
}

// One warp per query, 8 warps/block, NB neighbors batched. Channel ownership:
// c = V*lane + r so weight reads are LDS.128/LDS.64.
template <int CIN, int CMID, int COUT, int NB>
__device__ __forceinline__ void mlp_impl(int qblk,
        const float* __restrict__ x_src, const float* __restrict__ pos_src,
        const float* __restrict__ pos_q, const int* __restrict__ nbr,
        const int* __restrict__ cnt, float* __restrict__ out,
        const float* __restrict__ w1, const float* __restrict__ b1,
        const float* __restrict__ w2, const float* __restrict__ b2,
        int NSRC, int Mq) {
    constexpr int MSG = CIN + 3;
    constexpr int V1  = CMID / 32;
    constexpr int V2  = COUT / 32;
    constexpr int WPB = 8;

    extern __shared__ char smraw[];
    float* sw1  = (float*)smraw;             // MSG*CMID
    float* sb1  = sw1 + MSG * CMID;          // CMID
    float* sw2  = sb1 + CMID;                // CMID*COUT
    float* sb2  = sw2 + CMID * COUT;         // COUT
    float* smsg = sb2 + COUT;                // WPB*NB*MSG
    float* sh1  = smsg + WPB * NB * MSG;     // WPB*NB*CMID

    const int t = threadIdx.x;
    for (int i = t; i < MSG * CMID; i += TPB) sw1[i] = w1[i];
    for (int i = t; i < CMID; i += TPB) sb1[i] = b1[i];
    for (int i = t; i < CMID * COUT; i += TPB) sw2[i] = w2[i];
    for (int i = t; i < COUT; i += TPB) sb2[i] = b2[i];
    __syncthreads();

    const int w = t >> 5, lane = t & 31;
    const int q = qblk * WPB + w;
    const int b = q / Mq;
    const int kcnt = cnt[q];
    const float qx = pos_q[q * 3 + 0];
    const float qy = pos_q[q * 3 + 1];
    const float qz = pos_q[q * 3 + 2];
    float* msg = smsg + w * NB * MSG;
    float* h1  = sh1 + w * NB * CMID;
    const int* nb_ptr = nbr + (size_t)q * KNBR;
    const float* xs = x_src + (size_t)b * NSRC * CIN;
    const float* ps = pos_src + (size_t)b * NSRC * 3;

    float bias1[V1], bias2[V2];
#pragma unroll
    for (int r = 0; r < V1; r++) bias1[r] = sb1[V1 * lane + r];
#pragma unroll
    for (int r = 0; r < V2; r++) bias2[r] = sb2[V2 * lane + r];

    float vmax[V2];
#pragma unroll
    for (int r = 0; r < V2; r++) vmax[r] = -INFINITY;

    for (int n0 = 0; n0 < kcnt; n0 += NB) {
        const int nv = min(NB, kcnt - n0);
        for (int e = lane; e < NB * MSG; e += 32) {
            int nbn = e / MSG, i = e - nbn * MSG;
            float v = 0.0f;
            if (nbn < nv) {
                int nid = nb_ptr[n0 + nbn];
                if (i < CIN) {
                    v = xs[(size_t)nid * CIN + i];
                } else {
                    float qc = (i == CIN) ? qx : ((i == CIN + 1) ? qy : qz);
                    v = ps[nid * 3 + (i - CIN)] - qc;
                }
            }
            msg[e] = v;
        }
        __syncwarp();
        // layer 1
        float acc[NB][V1];
#pragma unroll
        for (int nbn = 0; nbn < NB; nbn++)
#pragma unroll
            for (int r = 0; r < V1; r++) acc[nbn][r] = bias1[r];
        for (int i = 0; i < MSG; i++) {
            float wv[V1];
            vldf<V1>(wv, sw1 + i * CMID + V1 * lane);
#pragma unroll
            for (int nbn = 0; nbn < NB; nbn++) {
                float mv = msg[nbn * MSG + i];
#pragma unroll
                for (int r = 0; r < V1; r++)
                    acc[nbn][r] = fmaf(mv, wv[r], acc[nbn][r]);
            }
        }
#pragma unroll
        for (int nbn = 0; nbn < NB; nbn++) {
            float hv[V1];
#pragma unroll
            for (int r = 0; r < V1; r++) hv[r] = fmaxf(acc[nbn][r], 0.0f);
            vstf<V1>(h1 + nbn * CMID + V1 * lane, hv);
        }
        __syncwarp();
        // layer 2 + running max
        float acc2[NB][V2];
#pragma unroll
        for (int nbn = 0; nbn < NB; nbn++)
#pragma unroll
            for (int r = 0; r < V2; r++) acc2[nbn][r] = bias2[r];
        for (int j = 0; j < CMID; j++) {
            float wv[V2];
            vldf<V2>(wv, sw2 + j * COUT + V2 * lane);
#pragma unroll
            for (int nbn = 0; nbn < NB; nbn++) {
                float hv = h1[nbn * CMID + j];
#pragma unroll
                for (int r = 0; r < V2; r++)
                    acc2[nbn][r] = fmaf(hv, wv[r], acc2[nbn][r]);
            }
        }
#pragma unroll
        for (int nbn = 0; nbn < NB; nbn++) {
            if (nbn < nv) {
#pragma unroll
                for (int r = 0; r < V2; r++)
                    vmax[r] = fmaxf(vmax[r], acc2[nbn][r]);
            }
        }
        __syncwarp();
    }
    float ov[V2];
#pragma unroll
    for (int r = 0; r < V2; r++) ov[r] = (kcnt > 0) ? vmax[r] : 0.0f;
    vstf<V2>(out + (size_t)q * COUT + V2 * lane, ov);
}

static __host__ __device__ constexpr size_t mlp_bytes(int CIN, int CMID, int COUT, int NB) {
    int MSG = CIN + 3;
    return (size_t)(MSG * CMID + CMID + CMID * COUT + COUT +
                    8 * NB * MSG + 8 * NB * CMID) * 4;
}

// ------------------------------ pack role ----------------------------------
__device__ __forceinline__ void pack_impl(int rb, const float* __restrict__ p3,
                                          float* __restrict__ out) {
    const int X3  = BB * M3 * 128;
    const int P3S = BB * M3 * 3;
    int i = rb * TPB + threadIdx.x;
    if (i < P3S) out[X3 + i] = p3[i];
    if (i < BB * M3) out[X3 + P3S + i] = (float)(i >> 9);
}

// ------------------------------ kernels ------------------------------------
#define RSQ1 ((float)(0.2 * 0.2))
#define RSQ2 ((float)(0.4 * 0.4))
#define RSQ3 ((float)(1.0 * 1.0))

__global__ void __launch_bounds__(TPB)
fps1_kernel(const float* __restrict__ pos, float* __restrict__ p1) {
    fps_impl<N1, M1>(pos + (size_t)blockIdx.x * N1 * 3,
                     p1 + (size_t)blockIdx.x * M1 * 3);
}

// fps2 (8 blocks) | ballq1 (BB*M1 blocks)
__global__ void __launch_bounds__(TPB)
combo2_kernel(const float* __restrict__ pos, const float* __restrict__ p1,
              float* __restrict__ p2, int* __restrict__ nbr1, int* __restrict__ cnt1) {
    if (blockIdx.x < BB) {
        fps_impl<M1, M2>(p1 + (size_t)blockIdx.x * M1 * 3,
                         p2 + (size_t)blockIdx.x * M2 * 3);
    } else {
        ballq_impl<N1>(blockIdx.x - BB, pos, p1, nbr1, cnt1, RSQ1, M1);
    }
}

// fps3 (8) | mlp1 (BB*M1/8) | ballq2 (BB*M2)
__global__ void __launch_bounds__(TPB)
combo3_kernel(const float* __restrict__ pos, const float* __restrict__ p1,
              const float* __restrict__ p2, float* __restrict__ p3,
              const int* __restrict__ nbr1, const int* __restrict__ cnt1,
              float* __restrict__ x1, int* __restrict__ nbr2, int* __restrict__ cnt2,
              const float* __restrict__ w11, const float* __restrict__ b11,
              const float* __restrict__ w12, const float* __restrict__ b12) {
    const int bid = blockIdx.x;
    if (bid < BB) {
        fps_impl<M2, M3>(p2 + (size_t)bid * M2 * 3, p3 + (size_t)bid * M3 * 3);
    } else if (bid < BB + BB * M1 / 8) {
        mlp_impl<3, 32, 32, 8>(bid - BB, pos, pos, p1, nbr1, cnt1, x1,
                               w11, b11, w12, b12, N1, M1);
    } else {
        ballq_impl<M1>(bid - BB - BB * M1 / 8, p1, p2, nbr2, cnt2, RSQ2, M2);
    }
}

// mlp2 (BB*M2/8) | ballq3 (BB*M3) | pack (48)
__global__ void __launch_bounds__(TPB)
combo4_kernel(const float* __restrict__ x1, const float* __restrict__ p1,
              const float* __restrict__ p2, const float* __restrict__ p3,
              const int* __restrict__ nbr2, const int* __restrict__ cnt2,
              float* __restrict__ x2, int* __restrict__ nbr3, int* __restrict__ cnt3,
              float* __restrict__ out,
              const float* __restrict__ w21, const float* __restrict__ b21,
              const float* __restrict__ w22, const float* __restrict__ b22) {
    const int bid = blockIdx.x;
    constexpr int MLP2B = BB * M2 / 8;
    if (bid < MLP2B) {
        mlp_impl<32, 64, 64, 8>(bid, x1, p1, p2, nbr2, cnt2, x2,
                                w21, b21, w22, b22, M1, M2);
    } else if (bid < MLP2B + BB * M3) {
        ballq_impl<M2>(bid - MLP2B, p2, p3, nbr3, cnt3, RSQ3, M3);
    } else {
        pack_impl(bid - MLP2B - BB * M3, p3, out);
    }
}

__global__ void __launch_bounds__(TPB)
mlp3_kernel(const float* __restrict__ x2, const float* __restrict__ p2,
            const float* __restrict__ p3, const int* __restrict__ nbr3,
            const int* __restrict__ cnt3, float* __restrict__ out,
            const float* __restrict__ w31, const float* __restrict__ b31,
            const float* __restrict__ w32, const float* __restrict__ b32) {
    mlp_impl<64, 128, 128, 8>(blockIdx.x, x2, p2, p3, nbr3, cnt3, out,
                              w31, b31, w32, b32, M2, M3);
}

// ------------------------------ host launch --------------------------------
static inline size_t smax(size_t a, size_t b) { return a > b ? a : b; }

extern "C" void kernel_launch(void* const* d_in, const int* in_sizes, int n_in,
                              void* d_out, int out_size) {
    const float* pos = (const float*)d_in[0];
    const float* w11 = (const float*)d_in[2];
    const float* b11 = (const float*)d_in[3];
    const float* w12 = (const float*)d_in[4];
    const float* b12 = (const float*)d_in[5];
    const float* w21 = (const float*)d_in[6];
    const float* b21 = (const float*)d_in[7];
    const float* w22 = (const float*)d_in[8];
    const float* b22 = (const float*)d_in[9];
    const float* w31 = (const float*)d_in[10];
    const float* b31 = (const float*)d_in[11];
    const float* w32 = (const float*)d_in[12];
    const float* b32 = (const float*)d_in[13];
    float* out = (float*)d_out;

    float *p1, *x1, *p2, *x2, *p3;
    int *nbr1, *cnt1, *nbr2, *cnt2, *nbr3, *cnt3;
    cudaGetSymbolAddress((void**)&p1, g_p1);
    cudaGetSymbolAddress((void**)&x1, g_x1);
    cudaGetSymbolAddress((void**)&p2, g_p2);
    cudaGetSymbolAddress((void**)&x2, g_x2);
    cudaGetSymbolAddress((void**)&p3, g_p3);
    cudaGetSymbolAddress((void**)&nbr1, g_nbr1);
    cudaGetSymbolAddress((void**)&cnt1, g_cnt1);
    cudaGetSymbolAddress((void**)&nbr2, g_nbr2);
    cudaGetSymbolAddress((void**)&cnt2, g_cnt2);
    cudaGetSymbolAddress((void**)&nbr3, g_nbr3);
    cudaGetSymbolAddress((void**)&cnt3, g_cnt3);

    const size_t sz1 = fps_bytes(N1);                                   // ~49.3KB
    const size_t sz2 = smax(fps_bytes(M1), ballq_bytes(N1));            // ~32.8KB
    const size_t sz3 = smax(smax(fps_bytes(M2), mlp_bytes(3, 32, 32, 8)),
                            ballq_bytes(M1));                           // ~16.4KB
    const size_t sz4 = smax(mlp_bytes(32, 64, 64, 8), ballq_bytes(M2)); // ~51.2KB
    const size_t sz5 = mlp_bytes(64, 128, 128, 8);                      // ~150.8KB

    cudaFuncSetAttribute(fps1_kernel, cudaFuncAttributeMaxDynamicSharedMemorySize, (int)sz1);
    cudaFuncSetAttribute(combo2_kernel, cudaFuncAttributeMaxDynamicSharedMemorySize, (int)sz2);
    cudaFuncSetAttribute(combo3_kernel, cudaFuncAttributeMaxDynamicSharedMemorySize, (int)sz3);
    cudaFuncSetAttribute(combo4_kernel, cudaFuncAttributeMaxDynamicSharedMemorySize, (int)sz4);
    cudaFuncSetAttribute(mlp3_kernel, cudaFuncAttributeMaxDynamicSharedMemorySize, (int)sz5);

    fps1_kernel<<<BB, TPB, sz1>>>(pos, p1);
    combo2_kernel<<<BB + BB * M1, TPB, sz2>>>(pos, p1, p2, nbr1, cnt1);
    combo3_kernel<<<BB + BB * M1 / 8 + BB * M2, TPB, sz3>>>(
        pos, p1, p2, p3, nbr1, cnt1, x1, nbr2, cnt2, w11, b11, w12, b12);
    combo4_kernel<<<BB * M2 / 8 + BB * M3 + 48, TPB, sz4>>>(
        x1, p1, p2, p3, nbr2, cnt2, x2, nbr3, cnt3, out, w21, b21, w22, b22);
    mlp3_kernel<<<BB * M3 / 8, TPB, sz5>>>(
        x2, p2, p3, nbr3, cnt3, out, w31, b31, w32, b32);
}